// round 10
// baseline (speedup 1.0000x reference)
#include <cuda_runtime.h>
#include <cuda_bf16.h>
#include <math.h>

// Problem constants
#define BATCH  1024
#define NDIM   256
#define NENT   50000
#define ROWS   2048              // 2 matrices (head/tail) x 1024 rows
#define BM     128               // GEMM row tile
#define BE     128               // GEMM entity tile
#define NCB    ((NENT + BE - 1) / BE)   // 391 column blocks
#define NENTP  (NCB * BE)               // 50048 padded entity rows
#define LDA    40                // padded smem row stride in bf16 elems (80B = 20 banks)

// ---------------- device scratch (static: no allocation) ----------------
__device__ __align__(16) float g_mean[3 * NDIM];
__device__ __align__(16) float g_rstd[3 * NDIM];
__device__ __align__(16) float g_vec[ROWS * NDIM];                 // fp32 (for zlab)
__device__ __align__(16) __nv_bfloat16 g_vecb[ROWS * NDIM];        // bf16 GEMM A
__device__ __align__(16) __nv_bfloat16 g_entb[(size_t)NENTP * NDIM]; // bf16 GEMM B, zero-padded
__device__ float g_zlab[ROWS];
__device__ __align__(16) float g_part[(size_t)ROWS * NCB * 4];     // 12.8 MB moment partials
__device__ float g_rowtot[ROWS];

__device__ __forceinline__ void cpa16(void* smem, const void* g) {
    unsigned s = (unsigned)__cvta_generic_to_shared(smem);
    asm volatile("cp.async.cg.shared.global [%0], [%1], 16;\n" :: "r"(s), "l"(g));
}
__device__ __forceinline__ void ldsm4(unsigned& r0, unsigned& r1, unsigned& r2, unsigned& r3,
                                      const void* p) {
    unsigned a = (unsigned)__cvta_generic_to_shared(p);
    asm volatile("ldmatrix.sync.aligned.m8n8.x4.shared.b16 {%0,%1,%2,%3}, [%4];"
                 : "=r"(r0), "=r"(r1), "=r"(r2), "=r"(r3) : "r"(a));
}

// ---------------- K0: ent_w -> bf16 table (padded with zeros) ----------------
// grid = NENTP*256/8/256 = 6256 blocks, 256 threads; 8 elems (16B out) per thread
__global__ void k_entb(const float* __restrict__ ent_w) {
    int chunk = blockIdx.x * 256 + threadIdx.x;      // 0 .. 1,601,535
    int row   = chunk >> 5;
    int c8    = (chunk & 31) * 8;
    __nv_bfloat162 o[4];
    if (row < NENT) {
        const float4* s = (const float4*)(ent_w + (size_t)row * NDIM + c8);
        float4 v0 = s[0], v1 = s[1];
        o[0] = __floats2bfloat162_rn(v0.x, v0.y);
        o[1] = __floats2bfloat162_rn(v0.z, v0.w);
        o[2] = __floats2bfloat162_rn(v1.x, v1.y);
        o[3] = __floats2bfloat162_rn(v1.z, v1.w);
    } else {
        o[0] = o[1] = o[2] = o[3] = __floats2bfloat162_rn(0.f, 0.f);
    }
    *(uint4*)(g_entb + (size_t)row * NDIM + c8) = *(uint4*)o;
}

// ---------------- K1: batch-norm statistics ----------------
__global__ void k_bn(const int* __restrict__ facts,
                     const float* __restrict__ ent_w,
                     const float* __restrict__ rel_w) {
    int s = blockIdx.x >> 8;
    int d = blockIdx.x & 255;
    const float* tab = (s < 2) ? ent_w : rel_w;
    float sum = 0.f, sq = 0.f;
    for (int b = threadIdx.x; b < BATCH; b += 256) {
        int idx = facts[b * 3 + s];
        float x = tab[idx * NDIM + d];
        sum += x;
        sq  += x * x;
    }
    __shared__ float s1[256], s2[256];
    s1[threadIdx.x] = sum;
    s2[threadIdx.x] = sq;
    __syncthreads();
    for (int o = 128; o > 0; o >>= 1) {
        if (threadIdx.x < o) {
            s1[threadIdx.x] += s1[threadIdx.x + o];
            s2[threadIdx.x] += s2[threadIdx.x + o];
        }
        __syncthreads();
    }
    if (threadIdx.x == 0) {
        float m = s1[0] * (1.f / BATCH);
        float v = s2[0] * (1.f / BATCH) - m * m;
        g_mean[s * NDIM + d] = m;
        g_rstd[s * NDIM + d] = rsqrtf(v + 1e-5f);
    }
}

// ---------------- K2: alpha einsum -> head_vec / tail_vec (fp32 + bf16 copies) ----------------
__global__ void k_vec(const int* __restrict__ facts,
                      const float* __restrict__ ent_w,
                      const float* __restrict__ rel_w,
                      const float* __restrict__ bne_g, const float* __restrict__ bne_b,
                      const float* __restrict__ bnr_g, const float* __restrict__ bnr_b,
                      const int* __restrict__ arch) {
    int b = blockIdx.x;
    int l = threadIdx.x;
    __shared__ float af[64];
    int a = arch[l];
    af[l] = (a == 0) ? 0.f : ((a == 1) ? 1.f : -1.f);
    __syncthreads();

    int hI = facts[b * 3 + 0];
    int tI = facts[b * 3 + 1];
    int rI = facts[b * 3 + 2];

    float re[4], te[4], he[4];
#pragma unroll
    for (int i = 0; i < 4; i++) {
        int d = i * 64 + l;
        he[i] = (ent_w[hI * NDIM + d] - g_mean[d])            * g_rstd[d]            * bne_g[d] + bne_b[d];
        te[i] = (ent_w[tI * NDIM + d] - g_mean[NDIM + d])     * g_rstd[NDIM + d]     * bne_g[d] + bne_b[d];
        re[i] = (rel_w[rI * NDIM + d] - g_mean[2 * NDIM + d]) * g_rstd[2 * NDIM + d] * bnr_g[d] + bnr_b[d];
    }
    float hv[4] = {0.f, 0.f, 0.f, 0.f};
    float tv[4] = {0.f, 0.f, 0.f, 0.f};
#pragma unroll
    for (int i = 0; i < 4; i++) {
#pragma unroll
        for (int j = 0; j < 4; j++) {
            float rt = re[i] * te[j];
            float rh = re[i] * he[j];
#pragma unroll
            for (int k = 0; k < 4; k++) {
                hv[k] = fmaf(af[(i * 4 + j) * 4 + k], rt, hv[k]);
                tv[k] = fmaf(af[(i * 4 + k) * 4 + j], rh, tv[k]);
            }
        }
    }
#pragma unroll
    for (int k = 0; k < 4; k++) {
        int dh = b * NDIM + k * 64 + l;
        int dt = (BATCH + b) * NDIM + k * 64 + l;
        g_vec[dh]  = hv[k];
        g_vec[dt]  = tv[k];
        g_vecb[dh] = __float2bfloat16_rn(hv[k]);
        g_vecb[dt] = __float2bfloat16_rn(tv[k]);
    }
}

// ---------------- K3: label logits (exact fp32) ----------------
__global__ void k_zlab(const int* __restrict__ facts,
                       const float* __restrict__ ent_w) {
    int w    = threadIdx.x >> 5;
    int lane = threadIdx.x & 31;
    int rid  = blockIdx.x * 8 + w;
    int m    = rid >> 10;
    int b    = rid & 1023;
    int lab  = facts[b * 3 + m];
    float s = 0.f;
    for (int d = lane; d < NDIM; d += 32)
        s = fmaf(g_vec[rid * NDIM + d], ent_w[lab * NDIM + d], s);
#pragma unroll
    for (int o = 16; o > 0; o >>= 1)
        s += __shfl_xor_sync(0xffffffffu, s, o);
    if (lane == 0) g_zlab[rid] = s;
}

// ---------------- K4: bf16 tensor-core GEMM + exp-moment epilogue ----------------
// grid = (NCB, 16), 256 threads (8 warps, 4m x 2n), CTA 128x128, BK=32, 2-stage cp.async
__global__ __launch_bounds__(256, 2) void k_gemm() {
    __shared__ __align__(16) __nv_bfloat16 sA[2][BM * LDA];   // 2 x 10 KB
    __shared__ __align__(16) __nv_bfloat16 sB[2][BE * LDA];

    int tid  = threadIdx.x;
    int cb   = blockIdx.x;
    int rb   = blockIdx.y;
    int row0 = rb * BM;
    int col0 = cb * BE;

    int warp = tid >> 5;
    int lane = tid & 31;
    int wm   = warp >> 1;      // 0..3 -> 32-row slab
    int wn   = warp & 1;       // 0..1 -> 64-col slab
    int q    = lane >> 2;      // 0..7
    int p    = lane & 3;       // 0..3

    // cp.async mapping: thread -> (row, 16-elem half), 2 x 16B per matrix
    int cr = tid >> 1;
    int ce = (tid & 1) * 16;
    const __nv_bfloat16* gA = g_vecb + (size_t)(row0 + cr) * NDIM + ce;
    const __nv_bfloat16* gB = g_entb + (size_t)(col0 + cr) * NDIM + ce;   // padded: always valid

    // ldmatrix lane addressing
    int a_row = (lane & 7) + ((lane >> 3) & 1) * 8;   // + base_m
    int a_kof = (lane >> 4) * 8;                      // + ks*16
    int b_row = (lane & 7) + ((lane >> 4) & 1) * 8;   // + base_n
    int b_kof = ((lane >> 3) & 1) * 8;                // + ks*16

    float acc[2][8][4];
#pragma unroll
    for (int i = 0; i < 2; i++)
#pragma unroll
        for (int j = 0; j < 8; j++)
#pragma unroll
            for (int c = 0; c < 4; c++) acc[i][j][c] = 0.f;

    // prologue: chunk 0 -> buf 0
    cpa16(&sA[0][cr * LDA + ce],     gA);
    cpa16(&sA[0][cr * LDA + ce + 8], gA + 8);
    cpa16(&sB[0][cr * LDA + ce],     gB);
    cpa16(&sB[0][cr * LDA + ce + 8], gB + 8);
    asm volatile("cp.async.commit_group;");

#pragma unroll 1
    for (int c = 0; c < 8; c++) {
        if (c + 1 < 8) {
            int nb = (c + 1) & 1;
            const __nv_bfloat16* pA = gA + (c + 1) * 32;
            const __nv_bfloat16* pB = gB + (c + 1) * 32;
            cpa16(&sA[nb][cr * LDA + ce],     pA);
            cpa16(&sA[nb][cr * LDA + ce + 8], pA + 8);
            cpa16(&sB[nb][cr * LDA + ce],     pB);
            cpa16(&sB[nb][cr * LDA + ce + 8], pB + 8);
            asm volatile("cp.async.commit_group;");
            asm volatile("cp.async.wait_group 1;");
        } else {
            asm volatile("cp.async.wait_group 0;");
        }
        __syncthreads();

        int bf = c & 1;
#pragma unroll
        for (int ks = 0; ks < 2; ks++) {
            unsigned a[2][4], b[4][4];
#pragma unroll
            for (int i = 0; i < 2; i++)
                ldsm4(a[i][0], a[i][1], a[i][2], a[i][3],
                      &sA[bf][(wm * 32 + i * 16 + a_row) * LDA + ks * 16 + a_kof]);
#pragma unroll
            for (int jj = 0; jj < 4; jj++)
                ldsm4(b[jj][0], b[jj][1], b[jj][2], b[jj][3],
                      &sB[bf][(wn * 64 + jj * 16 + b_row) * LDA + ks * 16 + b_kof]);
#pragma unroll
            for (int i = 0; i < 2; i++)
#pragma unroll
                for (int jj = 0; jj < 4; jj++)
#pragma unroll
                    for (int u = 0; u < 2; u++) {
                        int j = jj * 2 + u;
                        asm volatile(
                            "mma.sync.aligned.m16n8k16.row.col.f32.bf16.bf16.f32 "
                            "{%0,%1,%2,%3}, {%4,%5,%6,%7}, {%8,%9}, {%0,%1,%2,%3};"
                            : "+f"(acc[i][j][0]), "+f"(acc[i][j][1]),
                              "+f"(acc[i][j][2]), "+f"(acc[i][j][3])
                            : "r"(a[i][0]), "r"(a[i][1]), "r"(a[i][2]), "r"(a[i][3]),
                              "r"(b[jj][u * 2]), "r"(b[jj][u * 2 + 1]));
                    }
        }
        __syncthreads();
    }

    // Epilogue: masked exp power-sums S1..S4 per row over this 128-entity tile
    float mom[2][2][4];
#pragma unroll
    for (int i = 0; i < 2; i++)
#pragma unroll
        for (int s = 0; s < 2; s++)
#pragma unroll
            for (int n = 0; n < 4; n++) mom[i][s][n] = 0.f;

#pragma unroll
    for (int i = 0; i < 2; i++)
#pragma unroll
        for (int j = 0; j < 8; j++) {
            int cbase = col0 + wn * 64 + j * 8 + 2 * p;
#pragma unroll
            for (int s = 0; s < 2; s++)
#pragma unroll
                for (int u = 0; u < 2; u++) {
                    if (cbase + u < NENT) {
                        float e1 = __expf(acc[i][j][s * 2 + u]);
                        float e2 = e1 * e1;
                        mom[i][s][0] += e1;
                        mom[i][s][1] += e2;
                        mom[i][s][2] += e2 * e1;
                        mom[i][s][3] += e2 * e2;
                    }
                }
        }

    // quad reduce over p (lanes 4q+p share rows)
#pragma unroll
    for (int off = 1; off <= 2; off <<= 1)
#pragma unroll
        for (int i = 0; i < 2; i++)
#pragma unroll
            for (int s = 0; s < 2; s++)
#pragma unroll
                for (int n = 0; n < 4; n++)
                    mom[i][s][n] += __shfl_xor_sync(0xffffffffu, mom[i][s][n], off);

    // reduce across the 2 warp-columns through shared (reuse sA)
    float* red = (float*)sA;   // 1024 floats
    __syncthreads();
    if (p == 0) {
#pragma unroll
        for (int i = 0; i < 2; i++)
#pragma unroll
            for (int s = 0; s < 2; s++) {
                int rl = wm * 32 + i * 16 + s * 8 + q;
                *(float4*)&red[(wn * BM + rl) * 4] =
                    make_float4(mom[i][s][0], mom[i][s][1], mom[i][s][2], mom[i][s][3]);
            }
    }
    __syncthreads();
    if (tid < BM) {
        float4 u = *(float4*)&red[tid * 4];
        float4 v = *(float4*)&red[(BM + tid) * 4];
        float4 o = make_float4(u.x + v.x, u.y + v.y, u.z + v.z, u.w + v.w);
        *(float4*)&g_part[((size_t)(row0 + tid) * NCB + cb) * 4] = o;
    }
}

// ---------------- K5: per-row finalize ----------------
__global__ void k_fin() {
    int row = blockIdx.x;
    int tid = threadIdx.x;
    float s[4] = {0.f, 0.f, 0.f, 0.f};
    for (int cb = tid; cb < NCB; cb += 128) {
        const float* p = &g_part[((size_t)row * NCB + cb) * 4];
        s[0] += p[0]; s[1] += p[1]; s[2] += p[2]; s[3] += p[3];
    }
    __shared__ float red[512];
#pragma unroll
    for (int n = 0; n < 4; n++) red[n * 128 + tid] = s[n];
    __syncthreads();
    for (int o = 64; o > 0; o >>= 1) {
        if (tid < o) {
#pragma unroll
            for (int n = 0; n < 4; n++) red[n * 128 + tid] += red[n * 128 + tid + o];
        }
        __syncthreads();
    }
    if (tid == 0) {
        float S1 = red[0], S2 = red[128], S3 = red[256], S4 = red[384];
        float z  = g_zlab[row];
        float inv1 = 1.0f / S1;
        float inv2 = inv1 * inv1;
        float r2 = S2 * inv2;
        float r3 = S3 * inv2 * inv1;
        float r4 = S4 * inv2 * inv2;
        float sum_log1mp = -(1.0f + 0.5f * r2 + (1.0f / 3.0f) * r3 + 0.25f * r4);
        float plab = __expf(z) * inv1;
        float T = (z - logf(S1)) + sum_log1mp - log1pf(-plab);
        g_rowtot[row] = T;
    }
}

// ---------------- K6: final scalar ----------------
__global__ void k_loss(float* __restrict__ out) {
    __shared__ float red[1024];
    int tid = threadIdx.x;
    red[tid] = g_rowtot[tid] + g_rowtot[tid + 1024];
    __syncthreads();
    for (int o = 512; o > 0; o >>= 1) {
        if (tid < o) red[tid] += red[tid + o];
        __syncthreads();
    }
    if (tid == 0) out[0] = -red[0] * (1.0f / ((float)BATCH * (float)NENT));
}

// ---------------- launch ----------------
extern "C" void kernel_launch(void* const* d_in, const int* in_sizes, int n_in,
                              void* d_out, int out_size) {
    const int*   facts = (const int*)d_in[0];
    const int*   arch  = (const int*)d_in[1];
    const float* ent_w = (const float*)d_in[2];
    const float* rel_w = (const float*)d_in[3];
    const float* bne_g = (const float*)d_in[4];
    const float* bne_b = (const float*)d_in[5];
    const float* bnr_g = (const float*)d_in[6];
    const float* bnr_b = (const float*)d_in[7];
    float* out = (float*)d_out;

    k_entb<<<NENTP * 32 / 256, 256>>>(ent_w);
    k_bn<<<3 * 256, 256>>>(facts, ent_w, rel_w);
    k_vec<<<BATCH, 64>>>(facts, ent_w, rel_w, bne_g, bne_b, bnr_g, bnr_b, arch);
    k_zlab<<<256, 256>>>(facts, ent_w);
    dim3 gg(NCB, 16);
    k_gemm<<<gg, 256>>>();
    k_fin<<<ROWS, 128>>>();
    k_loss<<<1, 1024>>>(out);
}

// round 16
// speedup vs baseline: 1.5829x; 1.5829x over previous
#include <cuda_runtime.h>
#include <cuda_fp16.h>
#include <math.h>
#include <stdint.h>

// Problem constants
#define BATCH  1024
#define NDIM   256
#define NENT   50000
#define ROWS   2048
#define BM     128
#define BE     128
#define NCB    ((NENT + BE - 1) / BE)   // 391
#define NENTP  (NCB * BE)               // 50048
#define NRT    (ROWS / BM)              // 16

// k_gemm smem layout (halves strides padded: row step ≡ 4 banks mod 32 -> ldmatrix conflict-free)
#define LDB    264                       // B row stride in halves (528B)
#define LDAh   72                        // A row stride in halves (144B)
#define SMEM_B_OFF   0
#define SMEM_B_BYTES (BE * LDB * 2)      // 67584
#define SMEM_A_OFF   SMEM_B_BYTES
#define ABUF_BYTES   (BM * LDAh * 2)     // 18432
#define SMEM_RED_OFF (SMEM_A_OFF + 2 * ABUF_BYTES)   // 104448
#define SMEM_TOTAL   (SMEM_RED_OFF + 4096)           // 108544

// ---------------- device scratch (static: no allocation) ----------------
__device__ __align__(16) float g_mean[3 * NDIM];
__device__ __align__(16) float g_rstd[3 * NDIM];
__device__ __align__(16) __half g_vech[ROWS * NDIM];            // fp16 A
__device__ __align__(16) __half g_enth[(size_t)NENTP * NDIM];   // fp16 B, zero-padded
__device__ float g_zlab[ROWS];
__device__ __align__(16) float g_part[(size_t)ROWS * NCB * 4];
__device__ float g_rowtot[ROWS];

// ---------------- PTX helpers ----------------
__device__ __forceinline__ void cpa16(void* smem, const void* g) {
    unsigned s = (unsigned)__cvta_generic_to_shared(smem);
    asm volatile("cp.async.cg.shared.global [%0], [%1], 16;\n" :: "r"(s), "l"(g));
}
__device__ __forceinline__ void ldsm4(unsigned& r0, unsigned& r1, unsigned& r2, unsigned& r3,
                                      const void* p) {
    unsigned a = (unsigned)__cvta_generic_to_shared(p);
    asm volatile("ldmatrix.sync.aligned.m8n8.x4.shared.b16 {%0,%1,%2,%3}, [%4];"
                 : "=r"(r0), "=r"(r1), "=r"(r2), "=r"(r3) : "r"(a));
}
__device__ __forceinline__ void mma_f16acc(unsigned& c0, unsigned& c1,
                                           unsigned a0, unsigned a1, unsigned a2, unsigned a3,
                                           unsigned b0, unsigned b1) {
    asm volatile(
        "mma.sync.aligned.m16n8k16.row.col.f16.f16.f16.f16 "
        "{%0,%1}, {%2,%3,%4,%5}, {%6,%7}, {%0,%1};"
        : "+r"(c0), "+r"(c1)
        : "r"(a0), "r"(a1), "r"(a2), "r"(a3), "r"(b0), "r"(b1));
}

// ---------------- K0: ent_w -> fp16 table (padded with zeros) ----------------
__global__ void k_enth(const float* __restrict__ ent_w) {
    int chunk = blockIdx.x * 256 + threadIdx.x;
    int row   = chunk >> 5;
    int c8    = (chunk & 31) * 8;
    __half2 o[4];
    if (row < NENT) {
        const float4* s = (const float4*)(ent_w + (size_t)row * NDIM + c8);
        float4 v0 = s[0], v1 = s[1];
        o[0] = __floats2half2_rn(v0.x, v0.y);
        o[1] = __floats2half2_rn(v0.z, v0.w);
        o[2] = __floats2half2_rn(v1.x, v1.y);
        o[3] = __floats2half2_rn(v1.z, v1.w);
    } else {
        o[0] = o[1] = o[2] = o[3] = __floats2half2_rn(0.f, 0.f);
    }
    *(uint4*)(g_enth + (size_t)row * NDIM + c8) = *(uint4*)o;
}

// ---------------- K1: batch-norm statistics ----------------
__global__ void k_bn(const int* __restrict__ facts,
                     const float* __restrict__ ent_w,
                     const float* __restrict__ rel_w) {
    int s = blockIdx.x >> 8;
    int d = blockIdx.x & 255;
    const float* tab = (s < 2) ? ent_w : rel_w;
    float sum = 0.f, sq = 0.f;
    for (int b = threadIdx.x; b < BATCH; b += 256) {
        int idx = facts[b * 3 + s];
        float x = tab[idx * NDIM + d];
        sum += x;
        sq  += x * x;
    }
    __shared__ float s1[256], s2[256];
    s1[threadIdx.x] = sum;
    s2[threadIdx.x] = sq;
    __syncthreads();
    for (int o = 128; o > 0; o >>= 1) {
        if (threadIdx.x < o) {
            s1[threadIdx.x] += s1[threadIdx.x + o];
            s2[threadIdx.x] += s2[threadIdx.x + o];
        }
        __syncthreads();
    }
    if (threadIdx.x == 0) {
        float m = s1[0] * (1.f / BATCH);
        float v = s2[0] * (1.f / BATCH) - m * m;
        g_mean[s * NDIM + d] = m;
        g_rstd[s * NDIM + d] = rsqrtf(v + 1e-5f);
    }
}

// ---------------- K2: alpha einsum -> vecs (fp16) + fused label logits (fp32) ----------------
__global__ void k_vec(const int* __restrict__ facts,
                      const float* __restrict__ ent_w,
                      const float* __restrict__ rel_w,
                      const float* __restrict__ bne_g, const float* __restrict__ bne_b,
                      const float* __restrict__ bnr_g, const float* __restrict__ bnr_b,
                      const int* __restrict__ arch) {
    int b = blockIdx.x;
    int l = threadIdx.x;
    __shared__ float af[64];
    __shared__ float rz[2][64];
    int a = arch[l];
    af[l] = (a == 0) ? 0.f : ((a == 1) ? 1.f : -1.f);
    __syncthreads();

    int hI = facts[b * 3 + 0];
    int tI = facts[b * 3 + 1];
    int rI = facts[b * 3 + 2];

    float ehr[4], etr[4], re[4], te[4], he[4];
#pragma unroll
    for (int i = 0; i < 4; i++) {
        int d = i * 64 + l;
        ehr[i] = ent_w[hI * NDIM + d];
        etr[i] = ent_w[tI * NDIM + d];
        he[i] = (ehr[i] - g_mean[d])                          * g_rstd[d]            * bne_g[d] + bne_b[d];
        te[i] = (etr[i] - g_mean[NDIM + d])                   * g_rstd[NDIM + d]     * bne_g[d] + bne_b[d];
        re[i] = (rel_w[rI * NDIM + d] - g_mean[2 * NDIM + d]) * g_rstd[2 * NDIM + d] * bnr_g[d] + bnr_b[d];
    }
    float hv[4] = {0.f, 0.f, 0.f, 0.f};
    float tv[4] = {0.f, 0.f, 0.f, 0.f};
#pragma unroll
    for (int i = 0; i < 4; i++) {
#pragma unroll
        for (int j = 0; j < 4; j++) {
            float rt = re[i] * te[j];
            float rh = re[i] * he[j];
#pragma unroll
            for (int k = 0; k < 4; k++) {
                hv[k] = fmaf(af[(i * 4 + j) * 4 + k], rt, hv[k]);
                tv[k] = fmaf(af[(i * 4 + k) * 4 + j], rh, tv[k]);
            }
        }
    }
    float zh = 0.f, zt = 0.f;
#pragma unroll
    for (int k = 0; k < 4; k++) {
        g_vech[b * NDIM + k * 64 + l]           = __float2half_rn(hv[k]);
        g_vech[(BATCH + b) * NDIM + k * 64 + l] = __float2half_rn(tv[k]);
        zh = fmaf(hv[k], ehr[k], zh);
        zt = fmaf(tv[k], etr[k], zt);
    }
    rz[0][l] = zh;
    rz[1][l] = zt;
    __syncthreads();
    for (int o = 32; o > 0; o >>= 1) {
        if (l < o) {
            rz[0][l] += rz[0][l + o];
            rz[1][l] += rz[1][l + o];
        }
        __syncthreads();
    }
    if (l == 0) {
        g_zlab[b]         = rz[0][0];
        g_zlab[BATCH + b] = rz[1][0];
    }
}

// ---------------- K4: fp16 mma GEMM, resident B, streamed A + moment epilogue ----------------
// grid = NCB CTAs, 256 threads (8 warps, 4m x 2n). B tile staged once; 16 row tiles x 4 k-chunks.
__device__ __forceinline__ void stageA(char* smem, int buf, int rt, int kc, int tid) {
#pragma unroll
    for (int it = 0; it < 4; it++) {
        int idx = it * 256 + tid;           // 0..1023, 16B each
        int r = idx >> 3;
        int c = idx & 7;
        cpa16(smem + SMEM_A_OFF + buf * ABUF_BYTES + (r * LDAh + c * 8) * 2,
              g_vech + (size_t)(rt * BM + r) * NDIM + kc * 64 + c * 8);
    }
}

__global__ __launch_bounds__(256, 2) void k_gemm() {
    extern __shared__ __align__(1024) char smem[];
    __half* sB = (__half*)(smem + SMEM_B_OFF);
    float*  red = (float*)(smem + SMEM_RED_OFF);

    int tid  = threadIdx.x;
    int warp = tid >> 5;
    int lane = tid & 31;
    int cb   = blockIdx.x;
    int col0 = cb * BE;

    int wm = warp >> 1, wn = warp & 1;
    int q  = lane >> 2, p = lane & 3;
    int a_row = (lane & 7) + ((lane >> 3) & 1) * 8;
    int a_kof = (lane >> 4) * 8;
    int b_row = (lane & 7) + ((lane >> 4) & 1) * 8;
    int b_kof = ((lane >> 3) & 1) * 8;

    // stage B once: 128 rows x 256 halves = 4096 x 16B
    {
        const __half* gB = g_enth + (size_t)col0 * NDIM;
#pragma unroll
        for (int it = 0; it < 16; it++) {
            int chunk = it * 256 + tid;
            int r = chunk >> 5;
            int c = chunk & 31;
            cpa16(smem + SMEM_B_OFF + (r * LDB + c * 8) * 2, gB + (size_t)r * NDIM + c * 8);
        }
    }
    stageA(smem, 0, 0, 0, tid);
    asm volatile("cp.async.commit_group;");

    unsigned acc[2][8][2];
#pragma unroll
    for (int i = 0; i < 2; i++)
#pragma unroll
        for (int j = 0; j < 8; j++) { acc[i][j][0] = 0u; acc[i][j][1] = 0u; }

#pragma unroll 1
    for (int g = 0; g < NRT * 4; g++) {
        int rt = g >> 2, kc = g & 3, buf = g & 1;
        if (g + 1 < NRT * 4) {
            stageA(smem, buf ^ 1, (g + 1) >> 2, (g + 1) & 3, tid);
            asm volatile("cp.async.commit_group;");
            asm volatile("cp.async.wait_group 1;");
        } else {
            asm volatile("cp.async.wait_group 0;");
        }
        __syncthreads();

        const __half* bufA = (const __half*)(smem + SMEM_A_OFF + buf * ABUF_BYTES);
#pragma unroll
        for (int ks = 0; ks < 4; ks++) {
            unsigned a[2][4], b[4][4];
#pragma unroll
            for (int i = 0; i < 2; i++)
                ldsm4(a[i][0], a[i][1], a[i][2], a[i][3],
                      &bufA[(wm * 32 + i * 16 + a_row) * LDAh + ks * 16 + a_kof]);
#pragma unroll
            for (int jj = 0; jj < 4; jj++)
                ldsm4(b[jj][0], b[jj][1], b[jj][2], b[jj][3],
                      &sB[(wn * 64 + jj * 16 + b_row) * LDB + kc * 64 + ks * 16 + b_kof]);
#pragma unroll
            for (int i = 0; i < 2; i++)
#pragma unroll
                for (int jj = 0; jj < 4; jj++)
#pragma unroll
                    for (int u = 0; u < 2; u++) {
                        int j = jj * 2 + u;
                        mma_f16acc(acc[i][j][0], acc[i][j][1],
                                   a[i][0], a[i][1], a[i][2], a[i][3],
                                   b[jj][u * 2], b[jj][u * 2 + 1]);
                    }
        }
        __syncthreads();

        if (kc == 3) {
            // epilogue for row tile rt: masked exp power-sums S1..S4
            float mom[2][2][4];
#pragma unroll
            for (int i = 0; i < 2; i++)
#pragma unroll
                for (int s = 0; s < 2; s++)
#pragma unroll
                    for (int n = 0; n < 4; n++) mom[i][s][n] = 0.f;

#pragma unroll
            for (int i = 0; i < 2; i++)
#pragma unroll
                for (int j = 0; j < 8; j++) {
                    int cbase = col0 + wn * 64 + j * 8 + 2 * p;
#pragma unroll
                    for (int s = 0; s < 2; s++) {
                        __half2 h2 = *reinterpret_cast<__half2*>(&acc[i][j][s]);
                        float2 zz = __half22float2(h2);
#pragma unroll
                        for (int u = 0; u < 2; u++) {
                            float z = (u == 0) ? zz.x : zz.y;
                            if (cbase + u < NENT) {
                                float e1 = __expf(z);
                                float e2 = e1 * e1;
                                mom[i][s][0] += e1;
                                mom[i][s][1] += e2;
                                mom[i][s][2] += e2 * e1;
                                mom[i][s][3] += e2 * e2;
                            }
                        }
                    }
                }

#pragma unroll
            for (int off = 1; off <= 2; off <<= 1)
#pragma unroll
                for (int i = 0; i < 2; i++)
#pragma unroll
                    for (int s = 0; s < 2; s++)
#pragma unroll
                        for (int n = 0; n < 4; n++)
                            mom[i][s][n] += __shfl_xor_sync(0xffffffffu, mom[i][s][n], off);

            if (p == 0) {
#pragma unroll
                for (int i = 0; i < 2; i++)
#pragma unroll
                    for (int s = 0; s < 2; s++) {
                        int rl = wm * 32 + i * 16 + s * 8 + q;
                        *(float4*)&red[(wn * BM + rl) * 4] =
                            make_float4(mom[i][s][0], mom[i][s][1], mom[i][s][2], mom[i][s][3]);
                    }
            }
            __syncthreads();
            if (tid < BM) {
                float4 u0 = *(float4*)&red[tid * 4];
                float4 v0 = *(float4*)&red[(BM + tid) * 4];
                *(float4*)&g_part[((size_t)(rt * BM + tid) * NCB + cb) * 4] =
                    make_float4(u0.x + v0.x, u0.y + v0.y, u0.z + v0.z, u0.w + v0.w);
            }
            __syncthreads();

#pragma unroll
            for (int i = 0; i < 2; i++)
#pragma unroll
                for (int j = 0; j < 8; j++) { acc[i][j][0] = 0u; acc[i][j][1] = 0u; }
        }
    }
}

// ---------------- K5: per-row finalize ----------------
__global__ void k_fin() {
    int row = blockIdx.x;
    int tid = threadIdx.x;
    float s[4] = {0.f, 0.f, 0.f, 0.f};
    for (int cb = tid; cb < NCB; cb += 128) {
        const float* p = &g_part[((size_t)row * NCB + cb) * 4];
        s[0] += p[0]; s[1] += p[1]; s[2] += p[2]; s[3] += p[3];
    }
    __shared__ float red[512];
#pragma unroll
    for (int n = 0; n < 4; n++) red[n * 128 + tid] = s[n];
    __syncthreads();
    for (int o = 64; o > 0; o >>= 1) {
        if (tid < o) {
#pragma unroll
            for (int n = 0; n < 4; n++) red[n * 128 + tid] += red[n * 128 + tid + o];
        }
        __syncthreads();
    }
    if (tid == 0) {
        float S1 = red[0], S2 = red[128], S3 = red[256], S4 = red[384];
        float z  = g_zlab[row];
        float inv1 = 1.0f / S1;
        float inv2 = inv1 * inv1;
        float r2 = S2 * inv2;
        float r3 = S3 * inv2 * inv1;
        float r4 = S4 * inv2 * inv2;
        float sum_log1mp = -(1.0f + 0.5f * r2 + (1.0f / 3.0f) * r3 + 0.25f * r4);
        float plab = __expf(z) * inv1;
        float T = (z - logf(S1)) + sum_log1mp - log1pf(-plab);
        g_rowtot[row] = T;
    }
}

// ---------------- K6: final scalar ----------------
__global__ void k_loss(float* __restrict__ out) {
    __shared__ float red[1024];
    int tid = threadIdx.x;
    red[tid] = g_rowtot[tid] + g_rowtot[tid + 1024];
    __syncthreads();
    for (int o = 512; o > 0; o >>= 1) {
        if (tid < o) red[tid] += red[tid + o];
        __syncthreads();
    }
    if (tid == 0) out[0] = -red[0] * (1.0f / ((float)BATCH * (float)NENT));
}

// ---------------- launch ----------------
extern "C" void kernel_launch(void* const* d_in, const int* in_sizes, int n_in,
                              void* d_out, int out_size) {
    const int*   facts = (const int*)d_in[0];
    const int*   arch  = (const int*)d_in[1];
    const float* ent_w = (const float*)d_in[2];
    const float* rel_w = (const float*)d_in[3];
    const float* bne_g = (const float*)d_in[4];
    const float* bne_b = (const float*)d_in[5];
    const float* bnr_g = (const float*)d_in[6];
    const float* bnr_b = (const float*)d_in[7];
    float* out = (float*)d_out;

    cudaFuncSetAttribute(k_gemm, cudaFuncAttributeMaxDynamicSharedMemorySize, SMEM_TOTAL);

    k_enth<<<NENTP * 32 / 256, 256>>>(ent_w);
    k_bn<<<3 * 256, 256>>>(facts, ent_w, rel_w);
    k_vec<<<BATCH, 64>>>(facts, ent_w, rel_w, bne_g, bne_b, bnr_g, bnr_b, arch);
    k_gemm<<<NCB, 256, SMEM_TOTAL>>>();
    k_fin<<<ROWS, 128>>>();
    k_loss<<<1, 1024>>>(out);
}

// round 17
// speedup vs baseline: 1.6537x; 1.0447x over previous
#include <cuda_runtime.h>
#include <cuda_fp16.h>
#include <math.h>
#include <stdint.h>

// Problem constants
#define BATCH  1024
#define NDIM   256
#define NENT   50000
#define ROWS   2048
#define BM     128
#define BE     128
#define NCB    ((NENT + BE - 1) / BE)   // 391
#define NENTP  (NCB * BE)               // 50048
#define NRT    (ROWS / BM)              // 16
#define NCHUNK (NRT * 4)                // 64 (row tile x 64-k chunk)

// k_gemm smem layout (halves strides padded: row step ≡ 4 banks mod 32 -> ldmatrix conflict-free)
#define LDB    264                       // B row stride in halves (528B)
#define LDAh   72                        // A row stride in halves (144B)
#define SMEM_B_OFF   0
#define SMEM_B_BYTES (BE * LDB * 2)      // 67584
#define SMEM_A_OFF   SMEM_B_BYTES
#define ABUF_BYTES   (BM * LDAh * 2)     // 18432
#define SMEM_RED_OFF (SMEM_A_OFF + 2 * ABUF_BYTES)   // 104448
#define SMEM_TOTAL   (SMEM_RED_OFF + 4096)           // 108544

// ---------------- device scratch (static: no allocation) ----------------
__device__ __align__(16) float g_mean[3 * NDIM];
__device__ __align__(16) float g_rstd[3 * NDIM];
__device__ __align__(16) __half g_vech[ROWS * NDIM];            // fp16 A
__device__ __align__(16) __half g_enth[(size_t)NENTP * NDIM];   // fp16 B, zero-padded
__device__ float g_zlab[ROWS];
__device__ __align__(16) float g_part[(size_t)ROWS * NCB * 4];
__device__ float g_rowtot[ROWS];

// ---------------- PTX helpers ----------------
__device__ __forceinline__ void cpa16(void* smem, const void* g) {
    unsigned s = (unsigned)__cvta_generic_to_shared(smem);
    asm volatile("cp.async.cg.shared.global [%0], [%1], 16;\n" :: "r"(s), "l"(g));
}
__device__ __forceinline__ void ldsm4(unsigned& r0, unsigned& r1, unsigned& r2, unsigned& r3,
                                      const void* p) {
    unsigned a = (unsigned)__cvta_generic_to_shared(p);
    asm volatile("ldmatrix.sync.aligned.m8n8.x4.shared.b16 {%0,%1,%2,%3}, [%4];"
                 : "=r"(r0), "=r"(r1), "=r"(r2), "=r"(r3) : "r"(a));
}
__device__ __forceinline__ void mma_f16acc(unsigned& c0, unsigned& c1,
                                           unsigned a0, unsigned a1, unsigned a2, unsigned a3,
                                           unsigned b0, unsigned b1) {
    asm volatile(
        "mma.sync.aligned.m16n8k16.row.col.f16.f16.f16.f16 "
        "{%0,%1}, {%2,%3,%4,%5}, {%6,%7}, {%0,%1};"
        : "+r"(c0), "+r"(c1)
        : "r"(a0), "r"(a1), "r"(a2), "r"(a3), "r"(b0), "r"(b1));
}

// ---------------- K0: ent_w -> fp16 table (padded with zeros) ----------------
__global__ void k_enth(const float* __restrict__ ent_w) {
    int chunk = blockIdx.x * 256 + threadIdx.x;
    int row   = chunk >> 5;
    int c8    = (chunk & 31) * 8;
    __half2 o[4];
    if (row < NENT) {
        const float4* s = (const float4*)(ent_w + (size_t)row * NDIM + c8);
        float4 v0 = s[0], v1 = s[1];
        o[0] = __floats2half2_rn(v0.x, v0.y);
        o[1] = __floats2half2_rn(v0.z, v0.w);
        o[2] = __floats2half2_rn(v1.x, v1.y);
        o[3] = __floats2half2_rn(v1.z, v1.w);
    } else {
        o[0] = o[1] = o[2] = o[3] = __floats2half2_rn(0.f, 0.f);
    }
    *(uint4*)(g_enth + (size_t)row * NDIM + c8) = *(uint4*)o;
}

// ---------------- K1: batch-norm statistics ----------------
__global__ void k_bn(const int* __restrict__ facts,
                     const float* __restrict__ ent_w,
                     const float* __restrict__ rel_w) {
    int s = blockIdx.x >> 8;
    int d = blockIdx.x & 255;
    const float* tab = (s < 2) ? ent_w : rel_w;
    float sum = 0.f, sq = 0.f;
    for (int b = threadIdx.x; b < BATCH; b += 256) {
        int idx = facts[b * 3 + s];
        float x = tab[idx * NDIM + d];
        sum += x;
        sq  += x * x;
    }
    __shared__ float s1[256], s2[256];
    s1[threadIdx.x] = sum;
    s2[threadIdx.x] = sq;
    __syncthreads();
    for (int o = 128; o > 0; o >>= 1) {
        if (threadIdx.x < o) {
            s1[threadIdx.x] += s1[threadIdx.x + o];
            s2[threadIdx.x] += s2[threadIdx.x + o];
        }
        __syncthreads();
    }
    if (threadIdx.x == 0) {
        float m = s1[0] * (1.f / BATCH);
        float v = s2[0] * (1.f / BATCH) - m * m;
        g_mean[s * NDIM + d] = m;
        g_rstd[s * NDIM + d] = rsqrtf(v + 1e-5f);
    }
}

// ---------------- K2: alpha einsum -> vecs (fp16) + fused label logits (fp32) ----------------
__global__ void k_vec(const int* __restrict__ facts,
                      const float* __restrict__ ent_w,
                      const float* __restrict__ rel_w,
                      const float* __restrict__ bne_g, const float* __restrict__ bne_b,
                      const float* __restrict__ bnr_g, const float* __restrict__ bnr_b,
                      const int* __restrict__ arch) {
    int b = blockIdx.x;
    int l = threadIdx.x;
    __shared__ float af[64];
    __shared__ float rz[2][64];
    int a = arch[l];
    af[l] = (a == 0) ? 0.f : ((a == 1) ? 1.f : -1.f);
    __syncthreads();

    int hI = facts[b * 3 + 0];
    int tI = facts[b * 3 + 1];
    int rI = facts[b * 3 + 2];

    float ehr[4], etr[4], re[4], te[4], he[4];
#pragma unroll
    for (int i = 0; i < 4; i++) {
        int d = i * 64 + l;
        ehr[i] = ent_w[hI * NDIM + d];
        etr[i] = ent_w[tI * NDIM + d];
        he[i] = (ehr[i] - g_mean[d])                          * g_rstd[d]            * bne_g[d] + bne_b[d];
        te[i] = (etr[i] - g_mean[NDIM + d])                   * g_rstd[NDIM + d]     * bne_g[d] + bne_b[d];
        re[i] = (rel_w[rI * NDIM + d] - g_mean[2 * NDIM + d]) * g_rstd[2 * NDIM + d] * bnr_g[d] + bnr_b[d];
    }
    float hv[4] = {0.f, 0.f, 0.f, 0.f};
    float tv[4] = {0.f, 0.f, 0.f, 0.f};
#pragma unroll
    for (int i = 0; i < 4; i++) {
#pragma unroll
        for (int j = 0; j < 4; j++) {
            float rt = re[i] * te[j];
            float rh = re[i] * he[j];
#pragma unroll
            for (int k = 0; k < 4; k++) {
                hv[k] = fmaf(af[(i * 4 + j) * 4 + k], rt, hv[k]);
                tv[k] = fmaf(af[(i * 4 + k) * 4 + j], rh, tv[k]);
            }
        }
    }
    float zh = 0.f, zt = 0.f;
#pragma unroll
    for (int k = 0; k < 4; k++) {
        g_vech[b * NDIM + k * 64 + l]           = __float2half_rn(hv[k]);
        g_vech[(BATCH + b) * NDIM + k * 64 + l] = __float2half_rn(tv[k]);
        zh = fmaf(hv[k], ehr[k], zh);
        zt = fmaf(tv[k], etr[k], zt);
    }
    rz[0][l] = zh;
    rz[1][l] = zt;
    __syncthreads();
    for (int o = 32; o > 0; o >>= 1) {
        if (l < o) {
            rz[0][l] += rz[0][l + o];
            rz[1][l] += rz[1][l + o];
        }
        __syncthreads();
    }
    if (l == 0) {
        g_zlab[b]         = rz[0][0];
        g_zlab[BATCH + b] = rz[1][0];
    }
}

// ---------------- K4: fp16 mma GEMM, resident B, streamed A + moment epilogue ----------------
__device__ __forceinline__ void stageA(char* smem, int buf, int g, int tid) {
    int rt = g >> 2, kc = g & 3;
#pragma unroll
    for (int it = 0; it < 4; it++) {
        int idx = it * 256 + tid;           // 0..1023, 16B each
        int r = idx >> 3;
        int c = idx & 7;
        cpa16(smem + SMEM_A_OFF + buf * ABUF_BYTES + (r * LDAh + c * 8) * 2,
              g_vech + (size_t)(rt * BM + r) * NDIM + kc * 64 + c * 8);
    }
}

__global__ __launch_bounds__(256, 2) void k_gemm() {
    extern __shared__ __align__(1024) char smem[];
    __half* sB = (__half*)(smem + SMEM_B_OFF);
    float*  red = (float*)(smem + SMEM_RED_OFF);

    int tid  = threadIdx.x;
    int warp = tid >> 5;
    int lane = tid & 31;
    int cb   = blockIdx.x;
    int col0 = cb * BE;
    bool tail = (col0 + BE > NENT);      // only last CTA masks

    int wm = warp >> 1, wn = warp & 1;
    int q  = lane >> 2, p = lane & 3;
    int a_row = (lane & 7) + ((lane >> 3) & 1) * 8;
    int a_kof = (lane >> 4) * 8;
    int b_row = (lane & 7) + ((lane >> 4) & 1) * 8;
    int b_kof = ((lane >> 3) & 1) * 8;

    // stage B once: 128 rows x 256 halves
    {
        const __half* gB = g_enth + (size_t)col0 * NDIM;
#pragma unroll
        for (int it = 0; it < 16; it++) {
            int chunk = it * 256 + tid;
            int r = chunk >> 5;
            int c = chunk & 31;
            cpa16(smem + SMEM_B_OFF + (r * LDB + c * 8) * 2, gB + (size_t)r * NDIM + c * 8);
        }
    }
    stageA(smem, 0, 0, tid);
    asm volatile("cp.async.commit_group;");

    unsigned acc[2][8][2];
#pragma unroll
    for (int i = 0; i < 2; i++)
#pragma unroll
        for (int j = 0; j < 8; j++) { acc[i][j][0] = 0u; acc[i][j][1] = 0u; }

#pragma unroll 1
    for (int g = 0; g < NCHUNK; g++) {
        int rt = g >> 2, kc = g & 3, buf = g & 1;

        // chunk g's cp.async group is the newest (and only pending) one
        asm volatile("cp.async.wait_group 0;");
        __syncthreads();   // single barrier per chunk: also protects buf[(g-1)&1] reuse below

        // prefetch chunk g+1 into the buffer all warps finished reading at iter g-1
        if (g + 1 < NCHUNK) {
            stageA(smem, buf ^ 1, g + 1, tid);
            asm volatile("cp.async.commit_group;");
        }

        const __half* bufA = (const __half*)(smem + SMEM_A_OFF + buf * ABUF_BYTES);
#pragma unroll
        for (int ks = 0; ks < 4; ks++) {
            unsigned a[2][4], b[4][4];
#pragma unroll
            for (int i = 0; i < 2; i++)
                ldsm4(a[i][0], a[i][1], a[i][2], a[i][3],
                      &bufA[(wm * 32 + i * 16 + a_row) * LDAh + ks * 16 + a_kof]);
#pragma unroll
            for (int jj = 0; jj < 4; jj++)
                ldsm4(b[jj][0], b[jj][1], b[jj][2], b[jj][3],
                      &sB[(wn * 64 + jj * 16 + b_row) * LDB + kc * 64 + ks * 16 + b_kof]);
#pragma unroll
            for (int i = 0; i < 2; i++)
#pragma unroll
                for (int jj = 0; jj < 4; jj++)
#pragma unroll
                    for (int u = 0; u < 2; u++) {
                        int j = jj * 2 + u;
                        mma_f16acc(acc[i][j][0], acc[i][j][1],
                                   a[i][0], a[i][1], a[i][2], a[i][3],
                                   b[jj][u * 2], b[jj][u * 2 + 1]);
                    }
        }

        if (kc == 3) {
            // epilogue for row tile rt: exp power-sums S1..S4
            float mom[2][2][4];
#pragma unroll
            for (int i = 0; i < 2; i++)
#pragma unroll
                for (int s = 0; s < 2; s++)
#pragma unroll
                    for (int n = 0; n < 4; n++) mom[i][s][n] = 0.f;

            if (!tail) {
#pragma unroll
                for (int i = 0; i < 2; i++)
#pragma unroll
                    for (int j = 0; j < 8; j++)
#pragma unroll
                        for (int s = 0; s < 2; s++) {
                            float2 zz = __half22float2(*reinterpret_cast<__half2*>(&acc[i][j][s]));
                            float e1 = __expf(zz.x);
                            float f1 = __expf(zz.y);
                            float e2 = e1 * e1, f2 = f1 * f1;
                            mom[i][s][0] += e1 + f1;
                            mom[i][s][1] += e2 + f2;
                            mom[i][s][2] += e2 * e1 + f2 * f1;
                            mom[i][s][3] += e2 * e2 + f2 * f2;
                        }
            } else {
#pragma unroll
                for (int i = 0; i < 2; i++)
#pragma unroll
                    for (int j = 0; j < 8; j++) {
                        int cbase = col0 + wn * 64 + j * 8 + 2 * p;
#pragma unroll
                        for (int s = 0; s < 2; s++) {
                            float2 zz = __half22float2(*reinterpret_cast<__half2*>(&acc[i][j][s]));
#pragma unroll
                            for (int u = 0; u < 2; u++) {
                                float z = (u == 0) ? zz.x : zz.y;
                                if (cbase + u < NENT) {
                                    float e1 = __expf(z);
                                    float e2 = e1 * e1;
                                    mom[i][s][0] += e1;
                                    mom[i][s][1] += e2;
                                    mom[i][s][2] += e2 * e1;
                                    mom[i][s][3] += e2 * e2;
                                }
                            }
                        }
                    }
            }

#pragma unroll
            for (int off = 1; off <= 2; off <<= 1)
#pragma unroll
                for (int i = 0; i < 2; i++)
#pragma unroll
                    for (int s = 0; s < 2; s++)
#pragma unroll
                        for (int n = 0; n < 4; n++)
                            mom[i][s][n] += __shfl_xor_sync(0xffffffffu, mom[i][s][n], off);

            if (p == 0) {
#pragma unroll
                for (int i = 0; i < 2; i++)
#pragma unroll
                    for (int s = 0; s < 2; s++) {
                        int rl = wm * 32 + i * 16 + s * 8 + q;
                        *(float4*)&red[(wn * BM + rl) * 4] =
                            make_float4(mom[i][s][0], mom[i][s][1], mom[i][s][2], mom[i][s][3]);
                    }
            }
            __syncthreads();
            if (tid < BM) {
                float4 u0 = *(float4*)&red[tid * 4];
                float4 v0 = *(float4*)&red[(BM + tid) * 4];
                *(float4*)&g_part[((size_t)(rt * BM + tid) * NCB + cb) * 4] =
                    make_float4(u0.x + v0.x, u0.y + v0.y, u0.z + v0.z, u0.w + v0.w);
            }
            // no trailing barrier: the next chunk's top barrier orders red reuse

#pragma unroll
            for (int i = 0; i < 2; i++)
#pragma unroll
                for (int j = 0; j < 8; j++) { acc[i][j][0] = 0u; acc[i][j][1] = 0u; }
        }
    }
}

// ---------------- K5: per-row finalize ----------------
__global__ void k_fin() {
    int row = blockIdx.x;
    int tid = threadIdx.x;
    float s[4] = {0.f, 0.f, 0.f, 0.f};
    for (int cb = tid; cb < NCB; cb += 128) {
        const float* p = &g_part[((size_t)row * NCB + cb) * 4];
        s[0] += p[0]; s[1] += p[1]; s[2] += p[2]; s[3] += p[3];
    }
    __shared__ float red[512];
#pragma unroll
    for (int n = 0; n < 4; n++) red[n * 128 + tid] = s[n];
    __syncthreads();
    for (int o = 64; o > 0; o >>= 1) {
        if (tid < o) {
#pragma unroll
            for (int n = 0; n < 4; n++) red[n * 128 + tid] += red[n * 128 + tid + o];
        }
        __syncthreads();
    }
    if (tid == 0) {
        float S1 = red[0], S2 = red[128], S3 = red[256], S4 = red[384];
        float z  = g_zlab[row];
        float inv1 = 1.0f / S1;
        float inv2 = inv1 * inv1;
        float r2 = S2 * inv2;
        float r3 = S3 * inv2 * inv1;
        float r4 = S4 * inv2 * inv2;
        float sum_log1mp = -(1.0f + 0.5f * r2 + (1.0f / 3.0f) * r3 + 0.25f * r4);
        float plab = __expf(z) * inv1;
        float T = (z - logf(S1)) + sum_log1mp - log1pf(-plab);
        g_rowtot[row] = T;
    }
}

// ---------------- K6: final scalar ----------------
__global__ void k_loss(float* __restrict__ out) {
    __shared__ float red[1024];
    int tid = threadIdx.x;
    red[tid] = g_rowtot[tid] + g_rowtot[tid + 1024];
    __syncthreads();
    for (int o = 512; o > 0; o >>= 1) {
        if (tid < o) red[tid] += red[tid + o];
        __syncthreads();
    }
    if (tid == 0) out[0] = -red[0] * (1.0f / ((float)BATCH * (float)NENT));
}

// ---------------- launch ----------------
extern "C" void kernel_launch(void* const* d_in, const int* in_sizes, int n_in,
                              void* d_out, int out_size) {
    const int*   facts = (const int*)d_in[0];
    const int*   arch  = (const int*)d_in[1];
    const float* ent_w = (const float*)d_in[2];
    const float* rel_w = (const float*)d_in[3];
    const float* bne_g = (const float*)d_in[4];
    const float* bne_b = (const float*)d_in[5];
    const float* bnr_g = (const float*)d_in[6];
    const float* bnr_b = (const float*)d_in[7];
    float* out = (float*)d_out;

    cudaFuncSetAttribute(k_gemm, cudaFuncAttributeMaxDynamicSharedMemorySize, SMEM_TOTAL);

    k_enth<<<NENTP * 32 / 256, 256>>>(ent_w);
    k_bn<<<3 * 256, 256>>>(facts, ent_w, rel_w);
    k_vec<<<BATCH, 64>>>(facts, ent_w, rel_w, bne_g, bne_b, bnr_g, bnr_b, arch);
    k_gemm<<<NCB, 256, SMEM_TOTAL>>>();
    k_fin<<<ROWS, 128>>>();
    k_loss<<<1, 1024>>>(out);
}